// round 9
// baseline (speedup 1.0000x reference)
#include <cuda_runtime.h>

#define B_    32
#define SPAST 4095
#define SEQ   4096
#define H_    2048
#define NH_   16
#define HD_   128

// Scratch (no allocations allowed) -----------------------------------------
__device__ float g_qkv_part[16 * B_ * 3 * H_];  // QKV k-split partials (16 splits)
__device__ float g_qkv[B_ * 3 * H_];            // reduced qkv [32][6144]
__device__ float g_ctx[B_ * H_];                // attention output [32][2048]
__device__ float g_out_part[32 * B_ * H_];      // proj k-split partials (32 splits)

// Packed fp32x2 FMA (sm_103a FFMA2 — only reachable via PTX) ----------------
__device__ __forceinline__ void ffma2(unsigned long long& d,
                                      unsigned long long a,
                                      unsigned long long b) {
  asm("fma.rn.f32x2 %0, %1, %2, %0;" : "+l"(d) : "l"(a), "l"(b));
}
__device__ __forceinline__ unsigned long long dup2(float v) {
  unsigned long long r;
  asm("mov.b64 %0, {%1, %1};" : "=l"(r) : "f"(v));
  return r;
}
__device__ __forceinline__ void unpack2(float& lo, float& hi, unsigned long long v) {
  asm("mov.b64 {%0, %1}, %2;" : "=f"(lo), "=f"(hi) : "l"(v));
}

// ---------------------------------------------------------------------------
// Skinny GEMM with batch-paired FFMA2:
//   P[ks][b][n] = sum_{k in segment ks} X[b][k] * W[k][n]
// Block: 256 threads = 8 warps; warp w covers cols [w*128,(w+1)*128),
// lane owns 4 consecutive cols. Thread accumulates 16 batch rows as 8
// (even,odd) f32x2 pairs -> 32 FFMA2 per k instead of 64 FFMA.
// X staged TRANSPOSED xs[k][b]: one LDS.128 = 4 batches = 2 ready x-pairs.
// W float4 row load; per-col duplication is 4 ALU movs/k (off the FMA pipe).
// Grid: (N/1024, ksplit, 2)
// ---------------------------------------------------------------------------
__global__ __launch_bounds__(256) void gemm_skinny(
    const float* __restrict__ X, const float* __restrict__ W,
    float* __restrict__ P, int N, int kseg) {
  const int t = threadIdx.x;
  const int lane = t & 31;
  const int w = t >> 5;
  const int n0 = blockIdx.x * 1024 + w * 128 + lane * 4;
  const int kbeg = blockIdx.y * kseg;
  const int brow0 = blockIdx.z * 16;

  __shared__ float xs[32][20];  // [kk][bb]; rows are 80B -> every quad 16B-aligned

  unsigned long long acc[8][4];  // [batch-pair][col] = (b_even, b_odd)
#pragma unroll
  for (int bp = 0; bp < 8; bp++)
#pragma unroll
    for (int c = 0; c < 4; c++) acc[bp][c] = 0ull;

  for (int kc = 0; kc < kseg; kc += 32) {
    __syncthreads();
    // stage transposed X chunk: 16 rows x 32 k, coalesced gmem reads
#pragma unroll
    for (int r = t; r < 512; r += 256) {
      int bb = r >> 5, kk = r & 31;
      xs[kk][bb] = X[(brow0 + bb) * 2048 + kbeg + kc + kk];
    }
    __syncthreads();
#pragma unroll 4
    for (int kk = 0; kk < 32; kk++) {
      const float4 w4 = *reinterpret_cast<const float4*>(
          W + (size_t)(kbeg + kc + kk) * N + n0);
      unsigned long long wd[4];
      wd[0] = dup2(w4.x); wd[1] = dup2(w4.y);
      wd[2] = dup2(w4.z); wd[3] = dup2(w4.w);
#pragma unroll
      for (int g = 0; g < 4; g++) {  // batch quads: batches 4g..4g+3
        ulonglong2 xp = *reinterpret_cast<const ulonglong2*>(&xs[kk][g * 4]);
#pragma unroll
        for (int c = 0; c < 4; c++) {
          ffma2(acc[2 * g][c], xp.x, wd[c]);      // batches 4g, 4g+1
          ffma2(acc[2 * g + 1][c], xp.y, wd[c]);  // batches 4g+2, 4g+3
        }
      }
    }
  }
  float* p = P + (size_t)blockIdx.y * 32 * N;
#pragma unroll
  for (int bp = 0; bp < 8; bp++) {
    float4 lo, hi;
    unpack2(lo.x, hi.x, acc[bp][0]);
    unpack2(lo.y, hi.y, acc[bp][1]);
    unpack2(lo.z, hi.z, acc[bp][2]);
    unpack2(lo.w, hi.w, acc[bp][3]);
    *reinterpret_cast<float4*>(p + (size_t)(brow0 + 2 * bp) * N + n0) = lo;
    *reinterpret_cast<float4*>(p + (size_t)(brow0 + 2 * bp + 1) * N + n0) = hi;
  }
}

// out[b][n] = sum_ks P[ks][b][n] + bias[n]  (float4-vectorized)
__global__ void reduce_bias_kernel(const float4* __restrict__ P,
                                   const float4* __restrict__ bias,
                                   float4* __restrict__ out, int N4, int nsplit) {
  int i = blockIdx.x * 256 + threadIdx.x;
  int total4 = B_ * N4;
  if (i >= total4) return;
  float4 s = bias[i % N4];
  for (int k = 0; k < nsplit; k++) {
    float4 v = P[(size_t)k * total4 + i];
    s.x += v.x; s.y += v.y; s.z += v.z; s.w += v.w;
  }
  out[i] = s;
}

// ---------------------------------------------------------------------------
// Decode attention: one block per (b, h). 256 threads = 8 warps.
// 8-deep row unroll in both passes -> 8 independent LDG.128 in flight per warp.
// ---------------------------------------------------------------------------
__global__ __launch_bounds__(256) void attn_kernel(
    const float* __restrict__ past_key, const float* __restrict__ past_value) {
  const int h = blockIdx.x;
  const int b = blockIdx.y;
  const int t = threadIdx.x;
  const int lane = t & 31;
  const int wid = t >> 5;

  __shared__ float q_s[HD_];
  __shared__ float sc[SEQ];       // 16 KB scores
  __shared__ float red[32];
  __shared__ float ctxp[8][HD_];  // 4 KB partial ctx

  const float* qp = g_qkv + b * (3 * H_) + h * HD_;
  if (t < HD_) q_s[t] = qp[t] * 0.08838834764831845f;  // 1/sqrt(128)
  __syncthreads();

  const float4 qv = *reinterpret_cast<const float4*>(&q_s[lane * 4]);

  const float* kbase = past_key + ((size_t)b * SPAST) * H_ + h * HD_;
  const float* knew  = g_qkv + b * (3 * H_) + H_ + h * HD_;

  // ---- scores: warp handles rows wid*8+j, stride 64; MLP=8 ----
  for (int s0 = wid * 8; s0 < SEQ; s0 += 64) {
    float4 kv[8];
#pragma unroll
    for (int j = 0; j < 8; j++) {
      int s = s0 + j;
      const float* kr = (s < SPAST) ? (kbase + (size_t)s * H_) : knew;
      kv[j] = *reinterpret_cast<const float4*>(kr + lane * 4);
    }
#pragma unroll
    for (int j = 0; j < 8; j++) {
      float d = qv.x * kv[j].x + qv.y * kv[j].y + qv.z * kv[j].z + qv.w * kv[j].w;
      d += __shfl_xor_sync(0xffffffffu, d, 16);
      d += __shfl_xor_sync(0xffffffffu, d, 8);
      d += __shfl_xor_sync(0xffffffffu, d, 4);
      d += __shfl_xor_sync(0xffffffffu, d, 2);
      d += __shfl_xor_sync(0xffffffffu, d, 1);
      if (lane == 0) sc[s0 + j] = d;
    }
  }
  __syncthreads();

  // ---- softmax over sc[0..4095] ----
  float m = -3.0e38f;
  for (int i = t; i < SEQ; i += 256) m = fmaxf(m, sc[i]);
#pragma unroll
  for (int o = 16; o; o >>= 1) m = fmaxf(m, __shfl_xor_sync(0xffffffffu, m, o));
  if (lane == 0) red[wid] = m;
  __syncthreads();
  if (t == 0) {
    float mm = red[0];
    for (int ww = 1; ww < 8; ww++) mm = fmaxf(mm, red[ww]);
    red[8] = mm;
  }
  __syncthreads();
  const float gmax = red[8];

  float ls = 0.f;
  for (int i = t; i < SEQ; i += 256) {
    float e = __expf(sc[i] - gmax);
    sc[i] = e;
    ls += e;
  }
#pragma unroll
  for (int o = 16; o; o >>= 1) ls += __shfl_xor_sync(0xffffffffu, ls, o);
  if (lane == 0) red[16 + wid] = ls;
  __syncthreads();
  if (t == 0) {
    float ss = 0.f;
    for (int ww = 0; ww < 8; ww++) ss += red[16 + ww];
    red[24] = 1.0f / ss;
  }
  __syncthreads();
  const float inv = red[24];

  // ---- ctx = probs @ V, rows wid + 8*i, unroll 8 -> MLP=8 ----
  const float* vbase = past_value + ((size_t)b * SPAST) * H_ + h * HD_;
  const float* vnew  = g_qkv + b * (3 * H_) + 2 * H_ + h * HD_;
  float4 acc = make_float4(0.f, 0.f, 0.f, 0.f);
  for (int i = 0; i < SEQ / 8; i += 8) {
    float4 vv[8];
    float p[8];
#pragma unroll
    for (int j = 0; j < 8; j++) {
      int s = wid + (i + j) * 8;
      const float* vr = (s < SPAST) ? (vbase + (size_t)s * H_) : vnew;
      vv[j] = *reinterpret_cast<const float4*>(vr + lane * 4);
      p[j] = sc[s];
    }
#pragma unroll
    for (int j = 0; j < 8; j++) {
      acc.x += p[j] * vv[j].x;
      acc.y += p[j] * vv[j].y;
      acc.z += p[j] * vv[j].z;
      acc.w += p[j] * vv[j].w;
    }
  }
  *reinterpret_cast<float4*>(&ctxp[wid][lane * 4]) = acc;
  __syncthreads();
  if (t < HD_) {
    float v = 0.f;
#pragma unroll
    for (int ww = 0; ww < 8; ww++) v += ctxp[ww][t];
    g_ctx[b * H_ + h * HD_ + t] = v * inv;
  }
}

// ---------------------------------------------------------------------------
extern "C" void kernel_launch(void* const* d_in, const int* in_sizes, int n_in,
                              void* d_out, int out_size) {
  const float* x  = (const float*)d_in[0];   // [32,1,2048]
  const float* pk = (const float*)d_in[1];   // [32,4095,2048]
  const float* pv = (const float*)d_in[2];   // [32,4095,2048]
  const float* Wa = (const float*)d_in[3];   // [2048,6144]
  const float* ba = (const float*)d_in[4];   // [6144]
  const float* Wp = (const float*)d_in[5];   // [2048,2048]
  const float* bp = (const float*)d_in[6];   // [2048]
  float* out = (float*)d_out;                // [32,1,2048] fp32

  float *qkv_part, *qkv, *ctx, *out_part;
  cudaGetSymbolAddress((void**)&qkv_part, g_qkv_part);
  cudaGetSymbolAddress((void**)&qkv, g_qkv);
  cudaGetSymbolAddress((void**)&ctx, g_ctx);
  cudaGetSymbolAddress((void**)&out_part, g_out_part);

  // QKV: N=6144 -> 6 n-blocks, K split 16 (kseg=128), batch split 2 -> 192 blocks
  gemm_skinny<<<dim3(6, 16, 2), 256>>>(x, Wa, qkv_part, 3 * H_, 2048 / 16);
  reduce_bias_kernel<<<(B_ * 3 * H_ / 4 + 255) / 256, 256>>>(
      (const float4*)qkv_part, (const float4*)ba, (float4*)qkv, 3 * H_ / 4, 16);

  // Attention: one block per (head, batch) -> 512 blocks, single wave
  attn_kernel<<<dim3(NH_, B_), 256>>>(pk, pv);

  // Proj: N=2048 -> 2 n-blocks, K split 32 (kseg=64), batch split 2 -> 128 blocks
  gemm_skinny<<<dim3(2, 32, 2), 256>>>(ctx, Wp, out_part, H_, 2048 / 32);
  reduce_bias_kernel<<<(B_ * H_ / 4 + 255) / 256, 256>>>(
      (const float4*)out_part, (const float4*)bp, (float4*)out, H_ / 4, 32);
}